// round 8
// baseline (speedup 1.0000x reference)
#include <cuda_runtime.h>
#include <cuda_bf16.h>
#include <math.h>
#include <stdint.h>

// ---------------- constants ----------------
#define N_NODES  100000
#define N_EDGES  1600000
#define FEAT     128
#define N_GRAPHS 64
#define N_CLASSES 10

#define SCAN_BLK   1024
#define SCAN_NBLK  ((N_NODES + SCAN_BLK - 1) / SCAN_BLK)   // 98

// ---------------- device scratch ----------------
__device__ float g_S1[(size_t)N_NODES * FEAT];
__device__ float g_S2[(size_t)N_NODES * FEAT];
__device__ float g_S3[(size_t)N_NODES * FEAT];
__device__ __nv_bfloat16 g_B1[(size_t)N_NODES * FEAT];   // bf16 gather mirror

// pre-split concat weights (k-major u32 pairs): [pair 0..63][row 0..255]
__device__ uint32_t g_Wc1hi[64 * 256], g_Wc1lo[64 * 256];
__device__ uint32_t g_Wc2hi[64 * 256], g_Wc2lo[64 * 256];

__device__ int   g_src[N_EDGES];
__device__ int   g_dst[N_EDGES];
__device__ int   g_csr[N_EDGES];
__device__ int   g_batch[N_NODES];
__device__ int   g_indeg[N_NODES];
__device__ int   g_rowstart[N_NODES + 1];
__device__ int   g_pos[N_NODES];
__device__ float g_dinv[N_NODES];
__device__ float g_rcnt[N_NODES];
__device__ float g_pool[N_GRAPHS * FEAT];
__device__ int   g_gcnt[N_GRAPHS];
__device__ int   g_blocksum[SCAN_NBLK];
__device__ int   g_blockoff[SCAN_NBLK];
__device__ int   g_is64;

// ---------------- helpers ----------------
__device__ __forceinline__ void split2(float x, float y, uint32_t& hi, uint32_t& lo) {
    __nv_bfloat162 h = __floats2bfloat162_rn(x, y);
    float2 hf = __bfloat1622float2(h);
    __nv_bfloat162 l = __floats2bfloat162_rn(x - hf.x, y - hf.y);
    hi = *reinterpret_cast<uint32_t*>(&h);
    lo = *reinterpret_cast<uint32_t*>(&l);
}

__device__ __forceinline__ void mma_bf16(float* c, const uint32_t* a, const uint32_t* b) {
    asm volatile(
        "mma.sync.aligned.m16n8k16.row.col.f32.bf16.bf16.f32 "
        "{%0,%1,%2,%3}, {%4,%5,%6,%7}, {%8,%9}, {%0,%1,%2,%3};\n"
        : "+f"(c[0]), "+f"(c[1]), "+f"(c[2]), "+f"(c[3])
        : "r"(a[0]), "r"(a[1]), "r"(a[2]), "r"(a[3]), "r"(b[0]), "r"(b[1]));
}

// ---------------- index dtype detection ----------------
__global__ void detect_kernel(const void* ei) {
    const unsigned long long* p = (const unsigned long long*)ei;
    unsigned long long v = p[threadIdx.x];
    unsigned int hi = (unsigned int)(v >> 32);
    unsigned int any = __ballot_sync(0xffffffffu, hi != 0u);
    __shared__ int s_any;
    if (threadIdx.x == 0) s_any = 0;
    __syncthreads();
    if (any != 0u && (threadIdx.x & 31) == 0) atomicOr(&s_any, 1);
    __syncthreads();
    if (threadIdx.x == 0) g_is64 = s_any ? 0 : 1;
}

__global__ void zero_kernel() {
    int i = blockIdx.x * blockDim.x + threadIdx.x;
    if (i < N_NODES) g_indeg[i] = 0;
    if (i < N_GRAPHS * FEAT) g_pool[i] = 0.0f;
}

__global__ void convert_hist_kernel(const void* ei, const void* bt) {
    int i = blockIdx.x * blockDim.x + threadIdx.x;
    const int is64 = g_is64;
    if (i < N_EDGES) {
        int s, d;
        if (is64) {
            s = (int)((const long long*)ei)[i];
            d = (int)((const long long*)ei)[(size_t)N_EDGES + i];
        } else {
            s = ((const int*)ei)[i];
            d = ((const int*)ei)[N_EDGES + i];
        }
        g_src[i] = s;
        g_dst[i] = d;
        atomicAdd(&g_indeg[d], 1);
    }
    if (i < N_NODES) {
        g_batch[i] = is64 ? (int)((const long long*)bt)[i] : ((const int*)bt)[i];
    }
}

// ---------------- 3-phase multi-block scan ----------------
__global__ __launch_bounds__(SCAN_BLK) void scan1_kernel() {
    __shared__ int warp_s[32];
    int idx = blockIdx.x * SCAN_BLK + threadIdx.x;
    int v = (idx < N_NODES) ? g_indeg[idx] : 0;
#pragma unroll
    for (int o = 16; o > 0; o >>= 1) v += __shfl_down_sync(0xffffffffu, v, o);
    int wid = threadIdx.x >> 5, lane = threadIdx.x & 31;
    if (lane == 0) warp_s[wid] = v;
    __syncthreads();
    if (wid == 0) {
        int s = (lane < SCAN_BLK / 32) ? warp_s[lane] : 0;
#pragma unroll
        for (int o = 16; o > 0; o >>= 1) s += __shfl_down_sync(0xffffffffu, s, o);
        if (lane == 0) g_blocksum[blockIdx.x] = s;
    }
}

__global__ void scan2_kernel() {
    __shared__ int sm[SCAN_NBLK];
    int t = threadIdx.x;
    int v = (t < SCAN_NBLK) ? g_blocksum[t] : 0;
    if (t < SCAN_NBLK) sm[t] = v;
    __syncthreads();
    if (t == 0) {
        int run = 0;
        for (int i = 0; i < SCAN_NBLK; i++) { int c = sm[i]; sm[i] = run; run += c; }
        g_rowstart[N_NODES] = run;
    }
    __syncthreads();
    if (t < SCAN_NBLK) g_blockoff[t] = sm[t];
}

__global__ __launch_bounds__(SCAN_BLK) void scan3_kernel() {
    __shared__ int warp_s[32];
    int idx = blockIdx.x * SCAN_BLK + threadIdx.x;
    int wid = threadIdx.x >> 5, lane = threadIdx.x & 31;
    int c = (idx < N_NODES) ? g_indeg[idx] : 0;
    int v = c;
#pragma unroll
    for (int o = 1; o < 32; o <<= 1) {
        int u = __shfl_up_sync(0xffffffffu, v, o);
        if (lane >= o) v += u;
    }
    if (lane == 31) warp_s[wid] = v;
    __syncthreads();
    if (wid == 0) {
        int s = (lane < SCAN_BLK / 32) ? warp_s[lane] : 0;
#pragma unroll
        for (int o = 1; o < 32; o <<= 1) {
            int u = __shfl_up_sync(0xffffffffu, s, o);
            if (lane >= o) s += u;
        }
        if (lane < SCAN_BLK / 32) warp_s[lane] = s;
    }
    __syncthreads();
    int excl = v - c + (wid > 0 ? warp_s[wid - 1] : 0) + g_blockoff[blockIdx.x];
    if (idx < N_NODES) {
        g_rowstart[idx] = excl;
        g_pos[idx]      = excl;
        g_dinv[idx]     = rsqrtf((float)c + 1.0f);
        g_rcnt[idx]     = 1.0f / (float)max(c, 1);
    }
}

__global__ void scatter_kernel() {
    int e = blockIdx.x * blockDim.x + threadIdx.x;
    if (e < N_EDGES) {
        int d = g_dst[e];
        int p = atomicAdd(&g_pos[d], 1);
        g_csr[p] = g_src[e];
    }
}

// ---------------- weight prepack: concat [W1;W2] split hi/lo, k-major ----------------
__global__ void prepack_kernel(const float* __restrict__ W1, const float* __restrict__ W2,
                               uint32_t* __restrict__ hi, uint32_t* __restrict__ lo)
{
    int idx = blockIdx.x * blockDim.x + threadIdx.x;   // 0..16383
    int p = idx >> 8;         // k-pair 0..63
    int r = idx & 255;        // concat row 0..255
    const float* W = (r < 128) ? W1 : W2;
    int rr = r & 127;
    float x = W[rr * 128 + p * 2];
    float y = W[rr * 128 + p * 2 + 1];
    uint32_t h, l;
    split2(x, y, h, l);
    hi[p * 256 + r] = h;
    lo[p * 256 + r] = l;
}

// ---------------- GCN GEMM (old-style single-pass, split in kernel; overlapped) ----------
#define SMW 20
__global__ __launch_bounds__(256, 2) void gemm_gcn(
    const float* __restrict__ A, const float* __restrict__ W,
    float* __restrict__ out, __nv_bfloat16* __restrict__ outb, int M)
{
    __shared__ uint32_t sAhi[128][SMW], sAlo[128][SMW];
    __shared__ uint32_t sWhi[128][SMW], sWlo[128][SMW];

    const int t    = threadIdx.x;
    const int warp = t >> 5;
    const int lane = t & 31;
    const int wm   = warp >> 1;
    const int wn   = warp & 1;
    const int m0   = blockIdx.x * 128;
    const int r    = lane >> 2;
    const int kq   = lane & 3;

    float acc[2][8][4];
#pragma unroll
    for (int i = 0; i < 2; i++)
#pragma unroll
        for (int j = 0; j < 8; j++)
#pragma unroll
            for (int q = 0; q < 4; q++) acc[i][j][q] = 0.0f;

    for (int k0 = 0; k0 < 128; k0 += 32) {
#pragma unroll
        for (int i = 0; i < 4; i++) {
            int slot = t + i * 256;
            int row  = slot >> 3;
            int c4   = slot & 7;
            int ar   = m0 + row; if (ar >= M) ar = M - 1;
            float4 av = __ldg((const float4*)(A + (size_t)ar * 128 + k0 + c4 * 4));
            uint32_t h0, l0, h1, l1;
            split2(av.x, av.y, h0, l0);
            split2(av.z, av.w, h1, l1);
            sAhi[row][c4 * 2] = h0;  sAhi[row][c4 * 2 + 1] = h1;
            sAlo[row][c4 * 2] = l0;  sAlo[row][c4 * 2 + 1] = l1;
            float4 wv = __ldg((const float4*)(W + (size_t)row * 128 + k0 + c4 * 4));
            split2(wv.x, wv.y, h0, l0);
            split2(wv.z, wv.w, h1, l1);
            sWhi[row][c4 * 2] = h0;  sWhi[row][c4 * 2 + 1] = h1;
            sWlo[row][c4 * 2] = l0;  sWlo[row][c4 * 2 + 1] = l1;
        }
        __syncthreads();

#pragma unroll
        for (int kk = 0; kk < 32; kk += 16) {
            const int kw = kk >> 1;
            uint32_t ah[2][4], al[2][4];
#pragma unroll
            for (int mt = 0; mt < 2; mt++) {
                int mr = wm * 32 + mt * 16;
                ah[mt][0] = sAhi[mr + r][kw + kq];
                ah[mt][1] = sAhi[mr + r + 8][kw + kq];
                ah[mt][2] = sAhi[mr + r][kw + kq + 4];
                ah[mt][3] = sAhi[mr + r + 8][kw + kq + 4];
                al[mt][0] = sAlo[mr + r][kw + kq];
                al[mt][1] = sAlo[mr + r + 8][kw + kq];
                al[mt][2] = sAlo[mr + r][kw + kq + 4];
                al[mt][3] = sAlo[mr + r + 8][kw + kq + 4];
            }
#pragma unroll
            for (int g = 0; g < 2; g++) {
                uint32_t bh[4][2], bl[4][2];
#pragma unroll
                for (int n2 = 0; n2 < 4; n2++) {
                    int nr = wn * 64 + g * 32 + n2 * 8 + r;
                    bh[n2][0] = sWhi[nr][kw + kq];
                    bh[n2][1] = sWhi[nr][kw + kq + 4];
                    bl[n2][0] = sWlo[nr][kw + kq];
                    bl[n2][1] = sWlo[nr][kw + kq + 4];
                }
#pragma unroll
                for (int mt = 0; mt < 2; mt++)
#pragma unroll
                    for (int n2 = 0; n2 < 4; n2++) {
                        float* c = acc[mt][g * 4 + n2];
                        mma_bf16(c, ah[mt], bh[n2]);
                        mma_bf16(c, ah[mt], bl[n2]);
                        mma_bf16(c, al[mt], bh[n2]);
                    }
            }
        }
        __syncthreads();
    }

#pragma unroll
    for (int mt = 0; mt < 2; mt++) {
#pragma unroll
        for (int nt = 0; nt < 8; nt++) {
            int gcol = wn * 64 + nt * 8 + kq * 2;
            int grow = m0 + wm * 32 + mt * 16 + r;
            if (grow < M) {
                float v0 = acc[mt][nt][0], v1 = acc[mt][nt][1];
                float* p = out + (size_t)grow * 128 + gcol;
                p[0] = v0; p[1] = v1;
                *(__nv_bfloat162*)(outb + (size_t)grow * 128 + gcol) =
                    __floats2bfloat162_rn(v0, v1);
            }
            int grow2 = grow + 8;
            if (grow2 < M) {
                float v0 = acc[mt][nt][2], v1 = acc[mt][nt][3];
                float* p = out + (size_t)grow2 * 128 + gcol;
                p[0] = v0; p[1] = v1;
                *(__nv_bfloat162*)(outb + (size_t)grow2 * 128 + gcol) =
                    __floats2bfloat162_rn(v0, v1);
            }
        }
    }
}

// ---------------- wide SAGE GEMM: [Zl|Zr] = A @ [Wl|Wr]^T, pre-split weights ----------
// M-tile 64, N=256. Zl -> bf16 only; Zr -> fp32.
#define WSTR 12   // smem row stride (8 data u32 + 4 pad); conflict-free for (r,kq)

__global__ __launch_bounds__(256, 2) void gemm_wide(
    const float* __restrict__ A,
    const uint32_t* __restrict__ Whi, const uint32_t* __restrict__ Wlo,
    __nv_bfloat16* __restrict__ outLb, float* __restrict__ outR, int M)
{
    __shared__ uint32_t sAhi[64][WSTR], sAlo[64][WSTR];
    __shared__ uint32_t sWhi[256][WSTR], sWlo[256][WSTR];

    const int t    = threadIdx.x;
    const int warp = t >> 5;
    const int lane = t & 31;
    const int wm   = warp >> 2;        // 0..1  -> m base wm*32
    const int wn   = warp & 3;         // 0..3  -> n base wn*64
    const int m0   = blockIdx.x * 64;
    const int r    = lane >> 2;
    const int kq   = lane & 3;

    float acc[2][8][4];
#pragma unroll
    for (int i = 0; i < 2; i++)
#pragma unroll
        for (int j = 0; j < 8; j++)
#pragma unroll
            for (int q = 0; q < 4; q++) acc[i][j][q] = 0.0f;

    for (int k0 = 0; k0 < 128; k0 += 16) {
        // A tile 64x16 fp32 -> split
        {
            int row = t >> 2, c4 = t & 3;
            int ar = m0 + row; if (ar >= M) ar = M - 1;
            float4 av = __ldg((const float4*)(A + (size_t)ar * 128 + k0 + c4 * 4));
            uint32_t h0, l0, h1, l1;
            split2(av.x, av.y, h0, l0);
            split2(av.z, av.w, h1, l1);
            *(uint2*)&sAhi[row][c4 * 2] = make_uint2(h0, h1);
            *(uint2*)&sAlo[row][c4 * 2] = make_uint2(l0, l1);
        }
        // W tile: pairs kb..kb+7 x rows 0..255, k-major global (coalesced)
        {
            int kb = k0 >> 1;
#pragma unroll
            for (int i = 0; i < 8; i++) {
                sWhi[t][i] = __ldg(Whi + (kb + i) * 256 + t);
                sWlo[t][i] = __ldg(Wlo + (kb + i) * 256 + t);
            }
        }
        __syncthreads();

        uint32_t ah[2][4], al[2][4];
#pragma unroll
        for (int mt = 0; mt < 2; mt++) {
            int mr = wm * 32 + mt * 16;
            ah[mt][0] = sAhi[mr + r][kq];
            ah[mt][1] = sAhi[mr + r + 8][kq];
            ah[mt][2] = sAhi[mr + r][kq + 4];
            ah[mt][3] = sAhi[mr + r + 8][kq + 4];
            al[mt][0] = sAlo[mr + r][kq];
            al[mt][1] = sAlo[mr + r + 8][kq];
            al[mt][2] = sAlo[mr + r][kq + 4];
            al[mt][3] = sAlo[mr + r + 8][kq + 4];
        }
#pragma unroll
        for (int g = 0; g < 2; g++) {
            uint32_t bh[4][2], bl[4][2];
#pragma unroll
            for (int n2 = 0; n2 < 4; n2++) {
                int nr = wn * 64 + g * 32 + n2 * 8 + r;
                bh[n2][0] = sWhi[nr][kq];
                bh[n2][1] = sWhi[nr][kq + 4];
                bl[n2][0] = sWlo[nr][kq];
                bl[n2][1] = sWlo[nr][kq + 4];
            }
#pragma unroll
            for (int mt = 0; mt < 2; mt++)
#pragma unroll
                for (int n2 = 0; n2 < 4; n2++) {
                    float* c = acc[mt][g * 4 + n2];
                    mma_bf16(c, ah[mt], bh[n2]);
                    mma_bf16(c, ah[mt], bl[n2]);
                    mma_bf16(c, al[mt], bh[n2]);
                }
        }
        __syncthreads();
    }

    // epilogue: wn<2 -> Zl (bf16), wn>=2 -> Zr (fp32)
#pragma unroll
    for (int mt = 0; mt < 2; mt++) {
#pragma unroll
        for (int nt = 0; nt < 8; nt++) {
            int gcol = wn * 64 + nt * 8 + kq * 2;   // 0..255
            int grow = m0 + wm * 32 + mt * 16 + r;
            int grow2 = grow + 8;
            if (wn < 2) {
                if (grow < M)
                    *(__nv_bfloat162*)(outLb + (size_t)grow * 128 + gcol) =
                        __floats2bfloat162_rn(acc[mt][nt][0], acc[mt][nt][1]);
                if (grow2 < M)
                    *(__nv_bfloat162*)(outLb + (size_t)grow2 * 128 + gcol) =
                        __floats2bfloat162_rn(acc[mt][nt][2], acc[mt][nt][3]);
            } else {
                int cr = gcol - 128;
                if (grow < M) {
                    float* p = outR + (size_t)grow * 128 + cr;
                    p[0] = acc[mt][nt][0]; p[1] = acc[mt][nt][1];
                }
                if (grow2 < M) {
                    float* p = outR + (size_t)grow2 * 128 + cr;
                    p[0] = acc[mt][nt][2]; p[1] = acc[mt][nt][3];
                }
            }
        }
    }
}

// ---------------- GCN gather (bf16 neighbor reads, fp32 self + bias) ----------------
__device__ __forceinline__ void acc_bf16row(float4& acc, const __nv_bfloat16* __restrict__ hb,
                                            int s, int lane, float nm) {
    uint2 raw = __ldg((const uint2*)(hb + (size_t)s * 128) + lane);
    float2 p0 = __bfloat1622float2(*reinterpret_cast<__nv_bfloat162*>(&raw.x));
    float2 p1 = __bfloat1622float2(*reinterpret_cast<__nv_bfloat162*>(&raw.y));
    acc.x += p0.x * nm; acc.y += p0.y * nm;
    acc.z += p1.x * nm; acc.w += p1.y * nm;
}

__global__ __launch_bounds__(256) void gcn_gather_kernel(
    const __nv_bfloat16* __restrict__ xwb, const float* __restrict__ xw,
    float* __restrict__ out, const float* __restrict__ bias)
{
    int w = (blockIdx.x * blockDim.x + threadIdx.x) >> 5;
    int lane = threadIdx.x & 31;
    if (w >= N_NODES) return;
    int beg = g_rowstart[w], end = g_rowstart[w + 1];
    float dn = g_dinv[w];
    float4 acc = make_float4(0.f, 0.f, 0.f, 0.f);
    for (int b = beg; b < end; b += 32) {
        int nb = min(32, end - b);
        int s_l = 0; float d_l = 0.f;
        if (b + lane < end) { s_l = g_csr[b + lane]; d_l = g_dinv[s_l]; }
        int j = 0;
        for (; j + 4 <= nb; j += 4) {
            int s0 = __shfl_sync(0xffffffffu, s_l, j);
            int s1 = __shfl_sync(0xffffffffu, s_l, j + 1);
            int s2 = __shfl_sync(0xffffffffu, s_l, j + 2);
            int s3 = __shfl_sync(0xffffffffu, s_l, j + 3);
            float n0 = __shfl_sync(0xffffffffu, d_l, j) * dn;
            float n1 = __shfl_sync(0xffffffffu, d_l, j + 1) * dn;
            float n2 = __shfl_sync(0xffffffffu, d_l, j + 2) * dn;
            float n3 = __shfl_sync(0xffffffffu, d_l, j + 3) * dn;
            acc_bf16row(acc, xwb, s0, lane, n0);
            acc_bf16row(acc, xwb, s1, lane, n1);
            acc_bf16row(acc, xwb, s2, lane, n2);
            acc_bf16row(acc, xwb, s3, lane, n3);
        }
        for (; j < nb; j++) {
            int   s  = __shfl_sync(0xffffffffu, s_l, j);
            float nm = __shfl_sync(0xffffffffu, d_l, j) * dn;
            acc_bf16row(acc, xwb, s, lane, nm);
        }
    }
    float4 sv = *(const float4*)(xw + (size_t)w * 128 + lane * 4);
    float d2 = dn * dn;
    float4 bv = *(const float4*)(bias + lane * 4);
    acc.x += sv.x * d2 + bv.x; acc.y += sv.y * d2 + bv.y;
    acc.z += sv.z * d2 + bv.z; acc.w += sv.w * d2 + bv.w;
    *(float4*)(out + (size_t)w * 128 + lane * 4) = acc;
}

// ---------------- SAGE gather+add: out = mean(Zl) + bias + Zr ----------------
__global__ __launch_bounds__(256) void sage_gather_add_kernel(
    const __nv_bfloat16* __restrict__ Zl, const float* __restrict__ Zr,
    const float* __restrict__ bias, float* __restrict__ out)
{
    int w = (blockIdx.x * blockDim.x + threadIdx.x) >> 5;
    int lane = threadIdx.x & 31;
    if (w >= N_NODES) return;
    int beg = g_rowstart[w], end = g_rowstart[w + 1];
    float4 acc = make_float4(0.f, 0.f, 0.f, 0.f);
    for (int b = beg; b < end; b += 32) {
        int nb = min(32, end - b);
        int s_l = 0;
        if (b + lane < end) s_l = g_csr[b + lane];
        int j = 0;
        for (; j + 4 <= nb; j += 4) {
            int s0 = __shfl_sync(0xffffffffu, s_l, j);
            int s1 = __shfl_sync(0xffffffffu, s_l, j + 1);
            int s2 = __shfl_sync(0xffffffffu, s_l, j + 2);
            int s3 = __shfl_sync(0xffffffffu, s_l, j + 3);
            acc_bf16row(acc, Zl, s0, lane, 1.0f);
            acc_bf16row(acc, Zl, s1, lane, 1.0f);
            acc_bf16row(acc, Zl, s2, lane, 1.0f);
            acc_bf16row(acc, Zl, s3, lane, 1.0f);
        }
        for (; j < nb; j++) {
            int s = __shfl_sync(0xffffffffu, s_l, j);
            acc_bf16row(acc, Zl, s, lane, 1.0f);
        }
    }
    float rc = g_rcnt[w];
    float4 bv = *(const float4*)(bias + lane * 4);
    float4 rv = *(const float4*)(Zr + (size_t)w * 128 + lane * 4);
    acc.x = acc.x * rc + bv.x + rv.x;
    acc.y = acc.y * rc + bv.y + rv.y;
    acc.z = acc.z * rc + bv.z + rv.z;
    acc.w = acc.w * rc + bv.w + rv.w;
    *(float4*)(out + (size_t)w * 128 + lane * 4) = acc;
}

// ---------------- pooling ----------------
__device__ __forceinline__ int lower_bound_batch(int val) {
    int lo = 0, hi = N_NODES;
    while (lo < hi) {
        int mid = (lo + hi) >> 1;
        if (g_batch[mid] < val) lo = mid + 1; else hi = mid;
    }
    return lo;
}

__global__ void pool_kernel(const float* __restrict__ h) {
    int g = blockIdx.x;
    int part = blockIdx.y;
    int f = threadIdx.x;
    int lo = lower_bound_batch(g);
    int hi = lower_bound_batch(g + 1);
    float acc = 0.f;
    for (int n = lo + part; n < hi; n += 8) acc += h[(size_t)n * 128 + f];
    atomicAdd(&g_pool[g * 128 + f], acc);
    if (part == 0 && f == 0) g_gcnt[g] = max(hi - lo, 1);
}

// ---------------- classifier MLP + softmax ----------------
__global__ void mlp_kernel(
    const float* __restrict__ w0, const float* __restrict__ b0,
    const float* __restrict__ w1, const float* __restrict__ b1,
    const float* __restrict__ w2, const float* __restrict__ b2,
    const float* __restrict__ w3, const float* __restrict__ b3,
    const float* __restrict__ bn0g, const float* __restrict__ bn0b,
    const float* __restrict__ bn1g, const float* __restrict__ bn1b,
    const float* __restrict__ bn2g, const float* __restrict__ bn2b,
    float* __restrict__ out)
{
    __shared__ float sin_[128], h0[200], h1[100], h2[50], lg[10];
    int g = blockIdx.x, t = threadIdx.x;
    if (t < 128) sin_[t] = g_pool[g * 128 + t] / (float)g_gcnt[g];
    __syncthreads();
    const float bnc = rsqrtf(1.0f + 1e-5f);
    if (t < 200) {
        float s = b0[t];
        const float* wr = w0 + (size_t)t * 128;
#pragma unroll 4
        for (int k = 0; k < 128; k++) s += wr[k] * sin_[k];
        h0[t] = tanhf(s * bn0g[t] * bnc + bn0b[t]);
    }
    __syncthreads();
    if (t < 100) {
        float s = b1[t];
        const float* wr = w1 + (size_t)t * 200;
#pragma unroll 4
        for (int k = 0; k < 200; k++) s += wr[k] * h0[k];
        h1[t] = tanhf(s * bn1g[t] * bnc + bn1b[t]);
    }
    __syncthreads();
    if (t < 50) {
        float s = b2[t];
        const float* wr = w2 + (size_t)t * 100;
#pragma unroll 4
        for (int k = 0; k < 100; k++) s += wr[k] * h1[k];
        h2[t] = tanhf(s * bn2g[t] * bnc + bn2b[t]);
    }
    __syncthreads();
    if (t < 10) {
        float s = b3[t];
        const float* wr = w3 + (size_t)t * 50;
#pragma unroll
        for (int k = 0; k < 50; k++) s += wr[k] * h2[k];
        lg[t] = s;
    }
    __syncthreads();
    if (t == 0) {
        float m = lg[0];
        for (int c = 1; c < N_CLASSES; c++) m = fmaxf(m, lg[c]);
        float e[N_CLASSES];
        float sum = 0.f;
        for (int c = 0; c < N_CLASSES; c++) { e[c] = expf(lg[c] - m); sum += e[c]; }
        float inv = 1.0f / sum;
        for (int c = 0; c < N_CLASSES; c++) out[g * N_CLASSES + c] = e[c] * inv;
    }
}

// ---------------- launch ----------------
extern "C" void kernel_launch(void* const* d_in, const int* in_sizes, int n_in,
                              void* d_out, int out_size)
{
    const float* x       = (const float*)d_in[0];
    const void*  ei      = d_in[1];
    const void*  bt      = d_in[2];
    const float* gcn_w   = (const float*)d_in[3];
    const float* gcn_b   = (const float*)d_in[4];
    const float* s1_wl   = (const float*)d_in[5];
    const float* s1_bl   = (const float*)d_in[6];
    const float* s1_wr   = (const float*)d_in[7];
    const float* s2_wl   = (const float*)d_in[8];
    const float* s2_bl   = (const float*)d_in[9];
    const float* s2_wr   = (const float*)d_in[10];
    const float* c_w0 = (const float*)d_in[11]; const float* c_b0 = (const float*)d_in[12];
    const float* c_w1 = (const float*)d_in[13]; const float* c_b1 = (const float*)d_in[14];
    const float* c_w2 = (const float*)d_in[15]; const float* c_b2 = (const float*)d_in[16];
    const float* c_w3 = (const float*)d_in[17]; const float* c_b3 = (const float*)d_in[18];
    const float* bn0g = (const float*)d_in[19]; const float* bn0b = (const float*)d_in[20];
    const float* bn1g = (const float*)d_in[21]; const float* bn1b = (const float*)d_in[22];
    const float* bn2g = (const float*)d_in[23]; const float* bn2b = (const float*)d_in[24];
    float* out = (float*)d_out;

    float *S1, *S2, *S3;
    __nv_bfloat16 *B1;
    uint32_t *Wc1hi, *Wc1lo, *Wc2hi, *Wc2lo;
    cudaGetSymbolAddress((void**)&S1, g_S1);
    cudaGetSymbolAddress((void**)&S2, g_S2);
    cudaGetSymbolAddress((void**)&S3, g_S3);
    cudaGetSymbolAddress((void**)&B1, g_B1);
    cudaGetSymbolAddress((void**)&Wc1hi, g_Wc1hi);
    cudaGetSymbolAddress((void**)&Wc1lo, g_Wc1lo);
    cudaGetSymbolAddress((void**)&Wc2hi, g_Wc2hi);
    cudaGetSymbolAddress((void**)&Wc2lo, g_Wc2lo);

    static cudaStream_t s_side = nullptr;
    static cudaEvent_t  s_fork = nullptr, s_join = nullptr;
    if (s_side == nullptr) {
        cudaStreamCreateWithFlags(&s_side, cudaStreamNonBlocking);
        cudaEventCreateWithFlags(&s_fork, cudaEventDisableTiming);
        cudaEventCreateWithFlags(&s_join, cudaEventDisableTiming);
    }

    const int TB = 256;
    const int nodeBlocks   = (N_NODES + TB - 1) / TB;
    const int edgeBlocks   = (N_EDGES + TB - 1) / TB;
    const int gatherBlocks = (N_NODES + 7) / 8;
    const int gcnBlocks    = (N_NODES + 127) / 128;
    const int wideBlocks   = (N_NODES + 63) / 64;

    // weight prepack (cheap, independent)
    prepack_kernel<<<64, 256>>>(s1_wl, s1_wr, Wc1hi, Wc1lo);
    prepack_kernel<<<64, 256>>>(s2_wl, s2_wr, Wc2hi, Wc2lo);

    // fork: GCN GEMM overlaps CSR build
    detect_kernel<<<1, 256>>>(ei);
    cudaEventRecord(s_fork, 0);
    cudaStreamWaitEvent(s_side, s_fork, 0);
    gemm_gcn<<<gcnBlocks, 256, 0, s_side>>>(x, gcn_w, S1, B1, N_NODES);

    zero_kernel<<<nodeBlocks, TB>>>();
    convert_hist_kernel<<<edgeBlocks, TB>>>(ei, bt);
    scan1_kernel<<<SCAN_NBLK, SCAN_BLK>>>();
    scan2_kernel<<<1, 128>>>();
    scan3_kernel<<<SCAN_NBLK, SCAN_BLK>>>();
    scatter_kernel<<<edgeBlocks, TB>>>();

    cudaEventRecord(s_join, s_side);
    cudaStreamWaitEvent(0, s_join, 0);

    // GCN aggregate: S2 = norm-agg(B1) + self(S1)*dinv^2 + bias
    gcn_gather_kernel<<<gatherBlocks, 256>>>(B1, S1, S2, gcn_b);

    // SAGE1: [Z1l|Z1r] = S2 @ [Wl|Wr]; S3 = mean(Z1l) + bl + Z1r
    gemm_wide<<<wideBlocks, 256>>>(S2, Wc1hi, Wc1lo, B1, S1, N_NODES);
    sage_gather_add_kernel<<<gatherBlocks, 256>>>(B1, S1, s1_bl, S3);

    // SAGE2: [Z2l|Z2r] = S3 @ [Wl|Wr]; S2 = mean(Z2l) + bl + Z2r
    gemm_wide<<<wideBlocks, 256>>>(S3, Wc2hi, Wc2lo, B1, S1, N_NODES);
    sage_gather_add_kernel<<<gatherBlocks, 256>>>(B1, S1, s2_bl, S2);

    // pool + classifier
    dim3 pg(N_GRAPHS, 8);
    pool_kernel<<<pg, 128>>>(S2);
    mlp_kernel<<<N_GRAPHS, 256>>>(c_w0, c_b0, c_w1, c_b1, c_w2, c_b2, c_w3, c_b3,
                                  bn0g, bn0b, bn1g, bn1b, bn2g, bn2b, out);
}

// round 9
// speedup vs baseline: 1.0550x; 1.0550x over previous
#include <cuda_runtime.h>
#include <cuda_bf16.h>
#include <math.h>
#include <stdint.h>

// ---------------- constants ----------------
#define N_NODES  100000
#define N_EDGES  1600000
#define FEAT     128
#define N_GRAPHS 64
#define N_CLASSES 10

#define SCAN_BLK   1024
#define SCAN_NBLK  ((N_NODES + SCAN_BLK - 1) / SCAN_BLK)   // 98

// ---------------- device scratch ----------------
__device__ float g_S1[(size_t)N_NODES * FEAT];
__device__ float g_S2[(size_t)N_NODES * FEAT];
__device__ float g_S3[(size_t)N_NODES * FEAT];
__device__ __nv_bfloat16 g_B1[(size_t)N_NODES * FEAT];   // bf16 gather mirror A
__device__ __nv_bfloat16 g_B2[(size_t)N_NODES * FEAT];   // bf16 gather mirror B

// pre-split weights, k-major: [pair 0..63][row 0..127]
__device__ uint32_t g_Wg_hi[64 * 128],  g_Wg_lo[64 * 128];   // gcn_w
__device__ uint32_t g_W1l_hi[64 * 128], g_W1l_lo[64 * 128];  // sage1 Wl
__device__ uint32_t g_W1r_hi[64 * 128], g_W1r_lo[64 * 128];  // sage1 Wr
__device__ uint32_t g_W2l_hi[64 * 128], g_W2l_lo[64 * 128];  // sage2 Wl
__device__ uint32_t g_W2r_hi[64 * 128], g_W2r_lo[64 * 128];  // sage2 Wr

__device__ int   g_src[N_EDGES];
__device__ int   g_dst[N_EDGES];
__device__ int   g_csr[N_EDGES];
__device__ int   g_batch[N_NODES];
__device__ int   g_indeg[N_NODES];
__device__ int   g_rowstart[N_NODES + 1];
__device__ int   g_pos[N_NODES];
__device__ float g_dinv[N_NODES];
__device__ float g_rcnt[N_NODES];
__device__ float g_pool[N_GRAPHS * FEAT];
__device__ int   g_gcnt[N_GRAPHS];
__device__ int   g_blocksum[SCAN_NBLK];
__device__ int   g_blockoff[SCAN_NBLK];
__device__ int   g_is64;

// ---------------- helpers ----------------
__device__ __forceinline__ void split2(float x, float y, uint32_t& hi, uint32_t& lo) {
    __nv_bfloat162 h = __floats2bfloat162_rn(x, y);
    float2 hf = __bfloat1622float2(h);
    __nv_bfloat162 l = __floats2bfloat162_rn(x - hf.x, y - hf.y);
    hi = *reinterpret_cast<uint32_t*>(&h);
    lo = *reinterpret_cast<uint32_t*>(&l);
}

__device__ __forceinline__ void mma_bf16(float* c, const uint32_t* a, const uint32_t* b) {
    asm volatile(
        "mma.sync.aligned.m16n8k16.row.col.f32.bf16.bf16.f32 "
        "{%0,%1,%2,%3}, {%4,%5,%6,%7}, {%8,%9}, {%0,%1,%2,%3};\n"
        : "+f"(c[0]), "+f"(c[1]), "+f"(c[2]), "+f"(c[3])
        : "r"(a[0]), "r"(a[1]), "r"(a[2]), "r"(a[3]), "r"(b[0]), "r"(b[1]));
}

// ---------------- weight prepack: W[128,128] -> k-major split hi/lo ----------------
__global__ void prepack128(const float* __restrict__ W,
                           uint32_t* __restrict__ hi, uint32_t* __restrict__ lo)
{
    int idx = blockIdx.x * blockDim.x + threadIdx.x;   // 0..8191
    int p = idx >> 7;        // k-pair 0..63
    int r = idx & 127;       // row 0..127
    float x = W[r * 128 + p * 2];
    float y = W[r * 128 + p * 2 + 1];
    uint32_t h, l;
    split2(x, y, h, l);
    hi[p * 128 + r] = h;
    lo[p * 128 + r] = l;
}

// ---------------- index dtype detection ----------------
__global__ void detect_kernel(const void* ei) {
    const unsigned long long* p = (const unsigned long long*)ei;
    unsigned long long v = p[threadIdx.x];
    unsigned int hi = (unsigned int)(v >> 32);
    unsigned int any = __ballot_sync(0xffffffffu, hi != 0u);
    __shared__ int s_any;
    if (threadIdx.x == 0) s_any = 0;
    __syncthreads();
    if (any != 0u && (threadIdx.x & 31) == 0) atomicOr(&s_any, 1);
    __syncthreads();
    if (threadIdx.x == 0) g_is64 = s_any ? 0 : 1;
}

__global__ void zero_kernel() {
    int i = blockIdx.x * blockDim.x + threadIdx.x;
    if (i < N_NODES) g_indeg[i] = 0;
    if (i < N_GRAPHS * FEAT) g_pool[i] = 0.0f;
}

__global__ void convert_hist_kernel(const void* ei, const void* bt) {
    int i = blockIdx.x * blockDim.x + threadIdx.x;
    const int is64 = g_is64;
    if (i < N_EDGES) {
        int s, d;
        if (is64) {
            s = (int)((const long long*)ei)[i];
            d = (int)((const long long*)ei)[(size_t)N_EDGES + i];
        } else {
            s = ((const int*)ei)[i];
            d = ((const int*)ei)[N_EDGES + i];
        }
        g_src[i] = s;
        g_dst[i] = d;
        atomicAdd(&g_indeg[d], 1);
    }
    if (i < N_NODES) {
        g_batch[i] = is64 ? (int)((const long long*)bt)[i] : ((const int*)bt)[i];
    }
}

// ---------------- 3-phase multi-block scan ----------------
__global__ __launch_bounds__(SCAN_BLK) void scan1_kernel() {
    __shared__ int warp_s[32];
    int idx = blockIdx.x * SCAN_BLK + threadIdx.x;
    int v = (idx < N_NODES) ? g_indeg[idx] : 0;
#pragma unroll
    for (int o = 16; o > 0; o >>= 1) v += __shfl_down_sync(0xffffffffu, v, o);
    int wid = threadIdx.x >> 5, lane = threadIdx.x & 31;
    if (lane == 0) warp_s[wid] = v;
    __syncthreads();
    if (wid == 0) {
        int s = (lane < SCAN_BLK / 32) ? warp_s[lane] : 0;
#pragma unroll
        for (int o = 16; o > 0; o >>= 1) s += __shfl_down_sync(0xffffffffu, s, o);
        if (lane == 0) g_blocksum[blockIdx.x] = s;
    }
}

__global__ void scan2_kernel() {
    __shared__ int sm[SCAN_NBLK];
    int t = threadIdx.x;
    int v = (t < SCAN_NBLK) ? g_blocksum[t] : 0;
    if (t < SCAN_NBLK) sm[t] = v;
    __syncthreads();
    if (t == 0) {
        int run = 0;
        for (int i = 0; i < SCAN_NBLK; i++) { int c = sm[i]; sm[i] = run; run += c; }
        g_rowstart[N_NODES] = run;
    }
    __syncthreads();
    if (t < SCAN_NBLK) g_blockoff[t] = sm[t];
}

__global__ __launch_bounds__(SCAN_BLK) void scan3_kernel() {
    __shared__ int warp_s[32];
    int idx = blockIdx.x * SCAN_BLK + threadIdx.x;
    int wid = threadIdx.x >> 5, lane = threadIdx.x & 31;
    int c = (idx < N_NODES) ? g_indeg[idx] : 0;
    int v = c;
#pragma unroll
    for (int o = 1; o < 32; o <<= 1) {
        int u = __shfl_up_sync(0xffffffffu, v, o);
        if (lane >= o) v += u;
    }
    if (lane == 31) warp_s[wid] = v;
    __syncthreads();
    if (wid == 0) {
        int s = (lane < SCAN_BLK / 32) ? warp_s[lane] : 0;
#pragma unroll
        for (int o = 1; o < 32; o <<= 1) {
            int u = __shfl_up_sync(0xffffffffu, s, o);
            if (lane >= o) s += u;
        }
        if (lane < SCAN_BLK / 32) warp_s[lane] = s;
    }
    __syncthreads();
    int excl = v - c + (wid > 0 ? warp_s[wid - 1] : 0) + g_blockoff[blockIdx.x];
    if (idx < N_NODES) {
        g_rowstart[idx] = excl;
        g_pos[idx]      = excl;
        g_dinv[idx]     = rsqrtf((float)c + 1.0f);
        g_rcnt[idx]     = 1.0f / (float)max(c, 1);
    }
}

__global__ void scatter_kernel() {
    int e = blockIdx.x * blockDim.x + threadIdx.x;
    if (e < N_EDGES) {
        int d = g_dst[e];
        int p = atomicAdd(&g_pos[d], 1);
        g_csr[p] = g_src[e];
    }
}

// ---------------- bf16 split tensor-core GEMM, dual pass, prepacked W ----------------
// out[M,128] = A1@W1^T (+ A2@W2^T) (+bias); optional bf16 mirror.
#define SMW 20

__global__ __launch_bounds__(256, 2) void gemm_dual(
    const float* __restrict__ A1,
    const uint32_t* __restrict__ W1hi, const uint32_t* __restrict__ W1lo,
    const float* __restrict__ A2,
    const uint32_t* __restrict__ W2hi, const uint32_t* __restrict__ W2lo,
    const float* __restrict__ bias, float* __restrict__ out,
    __nv_bfloat16* __restrict__ outb, int M)
{
    __shared__ uint32_t sAhi[128][SMW], sAlo[128][SMW];
    __shared__ uint32_t sWhi[128][SMW], sWlo[128][SMW];

    const int t    = threadIdx.x;
    const int warp = t >> 5;
    const int lane = t & 31;
    const int wm   = warp >> 1;
    const int wn   = warp & 1;
    const int m0   = blockIdx.x * 128;
    const int r    = lane >> 2;
    const int kq   = lane & 3;

    float acc[2][8][4];
#pragma unroll
    for (int i = 0; i < 2; i++)
#pragma unroll
        for (int j = 0; j < 8; j++)
#pragma unroll
            for (int q = 0; q < 4; q++) acc[i][j][q] = 0.0f;

    const int npass = (A2 != nullptr) ? 2 : 1;
    for (int pass = 0; pass < npass; pass++) {
        const float*    A   = pass ? A2 : A1;
        const uint32_t* Whi = pass ? W2hi : W1hi;
        const uint32_t* Wlo = pass ? W2lo : W1lo;
        for (int k0 = 0; k0 < 128; k0 += 32) {
            // A tile 128x32 fp32 -> split (512 float4 slots / 256 threads)
#pragma unroll
            for (int i = 0; i < 2; i++) {
                int slot = t + i * 256;          // 0..511
                int row  = slot >> 2;            // 0..127
                int c4   = slot & 3;             // 4 float4 per... wait 32 cols = 8 float4
                // 128 rows x 8 float4 = 1024 slots needed with 2 floats4 each? No:
                // use 4-iteration form below instead.
                (void)row; (void)c4;
            }
            // (explicit 1024-slot fill, 4 slots per thread, A only)
#pragma unroll
            for (int i = 0; i < 4; i++) {
                int slot = t + i * 256;          // 0..1023
                int row  = slot >> 3;            // 0..127
                int c4   = slot & 7;             // float4 column within 32
                int ar   = m0 + row; if (ar >= M) ar = M - 1;
                float4 av = __ldg((const float4*)(A + (size_t)ar * 128 + k0 + c4 * 4));
                uint32_t h0, l0, h1, l1;
                split2(av.x, av.y, h0, l0);
                split2(av.z, av.w, h1, l1);
                sAhi[row][c4 * 2] = h0;  sAhi[row][c4 * 2 + 1] = h1;
                sAlo[row][c4 * 2] = l0;  sAlo[row][c4 * 2 + 1] = l1;
            }
            // W tile: prepacked k-major u32, coalesced copy (2048 u32 / array)
            {
                int kb = k0 >> 1;                // pair base 0,16,32,48
#pragma unroll
                for (int i = 0; i < 8; i++) {
                    int idx = t + i * 256;       // 0..2047
                    int row = idx & 127;
                    int w   = idx >> 7;          // 0..15
                    sWhi[row][w] = __ldg(Whi + (kb + w) * 128 + row);
                    sWlo[row][w] = __ldg(Wlo + (kb + w) * 128 + row);
                }
            }
            __syncthreads();

#pragma unroll
            for (int kk = 0; kk < 32; kk += 16) {
                const int kw = kk >> 1;
                uint32_t ah[2][4], al[2][4];
#pragma unroll
                for (int mt = 0; mt < 2; mt++) {
                    int mr = wm * 32 + mt * 16;
                    ah[mt][0] = sAhi[mr + r][kw + kq];
                    ah[mt][1] = sAhi[mr + r + 8][kw + kq];
                    ah[mt][2] = sAhi[mr + r][kw + kq + 4];
                    ah[mt][3] = sAhi[mr + r + 8][kw + kq + 4];
                    al[mt][0] = sAlo[mr + r][kw + kq];
                    al[mt][1] = sAlo[mr + r + 8][kw + kq];
                    al[mt][2] = sAlo[mr + r][kw + kq + 4];
                    al[mt][3] = sAlo[mr + r + 8][kw + kq + 4];
                }
#pragma unroll
                for (int g = 0; g < 2; g++) {
                    uint32_t bh[4][2], bl[4][2];
#pragma unroll
                    for (int n2 = 0; n2 < 4; n2++) {
                        int nr = wn * 64 + g * 32 + n2 * 8 + r;
                        bh[n2][0] = sWhi[nr][kw + kq];
                        bh[n2][1] = sWhi[nr][kw + kq + 4];
                        bl[n2][0] = sWlo[nr][kw + kq];
                        bl[n2][1] = sWlo[nr][kw + kq + 4];
                    }
#pragma unroll
                    for (int mt = 0; mt < 2; mt++)
#pragma unroll
                        for (int n2 = 0; n2 < 4; n2++) {
                            float* c = acc[mt][g * 4 + n2];
                            mma_bf16(c, ah[mt], bh[n2]);
                            mma_bf16(c, ah[mt], bl[n2]);
                            mma_bf16(c, al[mt], bh[n2]);
                        }
                }
            }
            __syncthreads();
        }
    }

#pragma unroll
    for (int mt = 0; mt < 2; mt++) {
#pragma unroll
        for (int nt = 0; nt < 8; nt++) {
            int gcol = wn * 64 + nt * 8 + kq * 2;
            float b0 = 0.f, b1 = 0.f;
            if (bias) { b0 = bias[gcol]; b1 = bias[gcol + 1]; }
            int grow = m0 + wm * 32 + mt * 16 + r;
            if (grow < M) {
                float v0 = acc[mt][nt][0] + b0;
                float v1 = acc[mt][nt][1] + b1;
                float* p = out + (size_t)grow * 128 + gcol;
                p[0] = v0; p[1] = v1;
                if (outb) *(__nv_bfloat162*)(outb + (size_t)grow * 128 + gcol) =
                    __floats2bfloat162_rn(v0, v1);
            }
            int grow2 = grow + 8;
            if (grow2 < M) {
                float v0 = acc[mt][nt][2] + b0;
                float v1 = acc[mt][nt][3] + b1;
                float* p = out + (size_t)grow2 * 128 + gcol;
                p[0] = v0; p[1] = v1;
                if (outb) *(__nv_bfloat162*)(outb + (size_t)grow2 * 128 + gcol) =
                    __floats2bfloat162_rn(v0, v1);
            }
        }
    }
}

// ---------------- CSR gathers (bf16 neighbor reads, fp32 accumulate) ----------------
__device__ __forceinline__ void acc_bf16row(float4& acc, const __nv_bfloat16* __restrict__ hb,
                                            int s, int lane, float nm) {
    uint2 raw = __ldg((const uint2*)(hb + (size_t)s * 128) + lane);
    float2 p0 = __bfloat1622float2(*reinterpret_cast<__nv_bfloat162*>(&raw.x));
    float2 p1 = __bfloat1622float2(*reinterpret_cast<__nv_bfloat162*>(&raw.y));
    acc.x += p0.x * nm; acc.y += p0.y * nm;
    acc.z += p1.x * nm; acc.w += p1.y * nm;
}

__global__ __launch_bounds__(256) void gcn_gather_kernel(
    const __nv_bfloat16* __restrict__ xwb, const float* __restrict__ xw,
    float* __restrict__ out, __nv_bfloat16* __restrict__ outb,
    const float* __restrict__ bias)
{
    int w = (blockIdx.x * blockDim.x + threadIdx.x) >> 5;
    int lane = threadIdx.x & 31;
    if (w >= N_NODES) return;
    int beg = g_rowstart[w], end = g_rowstart[w + 1];
    float dn = g_dinv[w];
    float4 acc = make_float4(0.f, 0.f, 0.f, 0.f);
    for (int b = beg; b < end; b += 32) {
        int nb = min(32, end - b);
        int s_l = 0; float d_l = 0.f;
        if (b + lane < end) { s_l = g_csr[b + lane]; d_l = g_dinv[s_l]; }
        for (int j = 0; j < nb; j++) {
            int   s  = __shfl_sync(0xffffffffu, s_l, j);
            float nm = __shfl_sync(0xffffffffu, d_l, j) * dn;
            acc_bf16row(acc, xwb, s, lane, nm);
        }
    }
    float4 sv = *(const float4*)(xw + (size_t)w * 128 + lane * 4);
    float d2 = dn * dn;
    float4 bv = *(const float4*)(bias + lane * 4);
    acc.x += sv.x * d2 + bv.x; acc.y += sv.y * d2 + bv.y;
    acc.z += sv.z * d2 + bv.z; acc.w += sv.w * d2 + bv.w;
    *(float4*)(out + (size_t)w * 128 + lane * 4) = acc;
    uint2 ob;
    __nv_bfloat162 q0 = __floats2bfloat162_rn(acc.x, acc.y);
    __nv_bfloat162 q1 = __floats2bfloat162_rn(acc.z, acc.w);
    ob.x = *reinterpret_cast<uint32_t*>(&q0);
    ob.y = *reinterpret_cast<uint32_t*>(&q1);
    *((uint2*)(outb + (size_t)w * 128) + lane) = ob;
}

__global__ __launch_bounds__(256) void sage_gather_kernel(
    const __nv_bfloat16* __restrict__ hb, float* __restrict__ out)
{
    int w = (blockIdx.x * blockDim.x + threadIdx.x) >> 5;
    int lane = threadIdx.x & 31;
    if (w >= N_NODES) return;
    int beg = g_rowstart[w], end = g_rowstart[w + 1];
    float4 acc = make_float4(0.f, 0.f, 0.f, 0.f);
    for (int b = beg; b < end; b += 32) {
        int nb = min(32, end - b);
        int s_l = 0;
        if (b + lane < end) s_l = g_csr[b + lane];
        for (int j = 0; j < nb; j++) {
            int s = __shfl_sync(0xffffffffu, s_l, j);
            acc_bf16row(acc, hb, s, lane, 1.0f);
        }
    }
    float rc = g_rcnt[w];
    acc.x *= rc; acc.y *= rc; acc.z *= rc; acc.w *= rc;
    *(float4*)(out + (size_t)w * 128 + lane * 4) = acc;
}

// ---------------- pooling ----------------
__device__ __forceinline__ int lower_bound_batch(int val) {
    int lo = 0, hi = N_NODES;
    while (lo < hi) {
        int mid = (lo + hi) >> 1;
        if (g_batch[mid] < val) lo = mid + 1; else hi = mid;
    }
    return lo;
}

__global__ void pool_kernel(const float* __restrict__ h) {
    int g = blockIdx.x;
    int part = blockIdx.y;
    int f = threadIdx.x;
    int lo = lower_bound_batch(g);
    int hi = lower_bound_batch(g + 1);
    float acc = 0.f;
    for (int n = lo + part; n < hi; n += 8) acc += h[(size_t)n * 128 + f];
    atomicAdd(&g_pool[g * 128 + f], acc);
    if (part == 0 && f == 0) g_gcnt[g] = max(hi - lo, 1);
}

// ---------------- classifier MLP + softmax ----------------
__global__ void mlp_kernel(
    const float* __restrict__ w0, const float* __restrict__ b0,
    const float* __restrict__ w1, const float* __restrict__ b1,
    const float* __restrict__ w2, const float* __restrict__ b2,
    const float* __restrict__ w3, const float* __restrict__ b3,
    const float* __restrict__ bn0g, const float* __restrict__ bn0b,
    const float* __restrict__ bn1g, const float* __restrict__ bn1b,
    const float* __restrict__ bn2g, const float* __restrict__ bn2b,
    float* __restrict__ out)
{
    __shared__ float sin_[128], h0[200], h1[100], h2[50], lg[10];
    int g = blockIdx.x, t = threadIdx.x;
    if (t < 128) sin_[t] = g_pool[g * 128 + t] / (float)g_gcnt[g];
    __syncthreads();
    const float bnc = rsqrtf(1.0f + 1e-5f);
    if (t < 200) {
        float s = b0[t];
        const float* wr = w0 + (size_t)t * 128;
#pragma unroll 4
        for (int k = 0; k < 128; k++) s += wr[k] * sin_[k];
        h0[t] = tanhf(s * bn0g[t] * bnc + bn0b[t]);
    }
    __syncthreads();
    if (t < 100) {
        float s = b1[t];
        const float* wr = w1 + (size_t)t * 200;
#pragma unroll 4
        for (int k = 0; k < 200; k++) s += wr[k] * h0[k];
        h1[t] = tanhf(s * bn1g[t] * bnc + bn1b[t]);
    }
    __syncthreads();
    if (t < 50) {
        float s = b2[t];
        const float* wr = w2 + (size_t)t * 100;
#pragma unroll 4
        for (int k = 0; k < 100; k++) s += wr[k] * h1[k];
        h2[t] = tanhf(s * bn2g[t] * bnc + bn2b[t]);
    }
    __syncthreads();
    if (t < 10) {
        float s = b3[t];
        const float* wr = w3 + (size_t)t * 50;
#pragma unroll
        for (int k = 0; k < 50; k++) s += wr[k] * h2[k];
        lg[t] = s;
    }
    __syncthreads();
    if (t == 0) {
        float m = lg[0];
        for (int c = 1; c < N_CLASSES; c++) m = fmaxf(m, lg[c]);
        float e[N_CLASSES];
        float sum = 0.f;
        for (int c = 0; c < N_CLASSES; c++) { e[c] = expf(lg[c] - m); sum += e[c]; }
        float inv = 1.0f / sum;
        for (int c = 0; c < N_CLASSES; c++) out[g * N_CLASSES + c] = e[c] * inv;
    }
}

// ---------------- launch ----------------
extern "C" void kernel_launch(void* const* d_in, const int* in_sizes, int n_in,
                              void* d_out, int out_size)
{
    const float* x       = (const float*)d_in[0];
    const void*  ei      = d_in[1];
    const void*  bt      = d_in[2];
    const float* gcn_w   = (const float*)d_in[3];
    const float* gcn_b   = (const float*)d_in[4];
    const float* s1_wl   = (const float*)d_in[5];
    const float* s1_bl   = (const float*)d_in[6];
    const float* s1_wr   = (const float*)d_in[7];
    const float* s2_wl   = (const float*)d_in[8];
    const float* s2_bl   = (const float*)d_in[9];
    const float* s2_wr   = (const float*)d_in[10];
    const float* c_w0 = (const float*)d_in[11]; const float* c_b0 = (const float*)d_in[12];
    const float* c_w1 = (const float*)d_in[13]; const float* c_b1 = (const float*)d_in[14];
    const float* c_w2 = (const float*)d_in[15]; const float* c_b2 = (const float*)d_in[16];
    const float* c_w3 = (const float*)d_in[17]; const float* c_b3 = (const float*)d_in[18];
    const float* bn0g = (const float*)d_in[19]; const float* bn0b = (const float*)d_in[20];
    const float* bn1g = (const float*)d_in[21]; const float* bn1b = (const float*)d_in[22];
    const float* bn2g = (const float*)d_in[23]; const float* bn2b = (const float*)d_in[24];
    float* out = (float*)d_out;

    float *S1, *S2, *S3;
    __nv_bfloat16 *B1, *B2;
    uint32_t *Wg_hi, *Wg_lo, *W1l_hi, *W1l_lo, *W1r_hi, *W1r_lo;
    uint32_t *W2l_hi, *W2l_lo, *W2r_hi, *W2r_lo;
    cudaGetSymbolAddress((void**)&S1, g_S1);
    cudaGetSymbolAddress((void**)&S2, g_S2);
    cudaGetSymbolAddress((void**)&S3, g_S3);
    cudaGetSymbolAddress((void**)&B1, g_B1);
    cudaGetSymbolAddress((void**)&B2, g_B2);
    cudaGetSymbolAddress((void**)&Wg_hi, g_Wg_hi);   cudaGetSymbolAddress((void**)&Wg_lo, g_Wg_lo);
    cudaGetSymbolAddress((void**)&W1l_hi, g_W1l_hi); cudaGetSymbolAddress((void**)&W1l_lo, g_W1l_lo);
    cudaGetSymbolAddress((void**)&W1r_hi, g_W1r_hi); cudaGetSymbolAddress((void**)&W1r_lo, g_W1r_lo);
    cudaGetSymbolAddress((void**)&W2l_hi, g_W2l_hi); cudaGetSymbolAddress((void**)&W2l_lo, g_W2l_lo);
    cudaGetSymbolAddress((void**)&W2r_hi, g_W2r_hi); cudaGetSymbolAddress((void**)&W2r_lo, g_W2r_lo);

    static cudaStream_t s_side = nullptr;
    static cudaEvent_t  s_fork = nullptr, s_join = nullptr;
    if (s_side == nullptr) {
        cudaStreamCreateWithFlags(&s_side, cudaStreamNonBlocking);
        cudaEventCreateWithFlags(&s_fork, cudaEventDisableTiming);
        cudaEventCreateWithFlags(&s_join, cudaEventDisableTiming);
    }

    const int TB = 256;
    const int nodeBlocks   = (N_NODES + TB - 1) / TB;
    const int edgeBlocks   = (N_EDGES + TB - 1) / TB;
    const int gatherBlocks = (N_NODES + 7) / 8;
    const int gemmBlocks   = (N_NODES + 127) / 128;

    // weight prepack (5x ~2us, before the fork so the side-stream GEMM sees them)
    prepack128<<<32, 256>>>(gcn_w, Wg_hi, Wg_lo);
    prepack128<<<32, 256>>>(s1_wl, W1l_hi, W1l_lo);
    prepack128<<<32, 256>>>(s1_wr, W1r_hi, W1r_lo);
    prepack128<<<32, 256>>>(s2_wl, W2l_hi, W2l_lo);
    prepack128<<<32, 256>>>(s2_wr, W2r_hi, W2r_lo);

    // fork: GCN GEMM overlaps CSR build
    detect_kernel<<<1, 256>>>(ei);
    cudaEventRecord(s_fork, 0);
    cudaStreamWaitEvent(s_side, s_fork, 0);
    gemm_dual<<<gemmBlocks, 256, 0, s_side>>>(x, Wg_hi, Wg_lo, nullptr, nullptr, nullptr,
                                              nullptr, S1, B1, N_NODES);

    zero_kernel<<<nodeBlocks, TB>>>();
    convert_hist_kernel<<<edgeBlocks, TB>>>(ei, bt);
    scan1_kernel<<<SCAN_NBLK, SCAN_BLK>>>();
    scan2_kernel<<<1, 128>>>();
    scan3_kernel<<<SCAN_NBLK, SCAN_BLK>>>();
    scatter_kernel<<<edgeBlocks, TB>>>();

    cudaEventRecord(s_join, s_side);
    cudaStreamWaitEvent(0, s_join, 0);

    // GCN aggregate
    gcn_gather_kernel<<<gatherBlocks, 256>>>(B1, S1, S2, B2, gcn_b);

    // SAGE1
    sage_gather_kernel<<<gatherBlocks, 256>>>(B2, S1);
    gemm_dual<<<gemmBlocks, 256>>>(S1, W1l_hi, W1l_lo, S2, W1r_hi, W1r_lo,
                                   s1_bl, S3, B1, N_NODES);

    // SAGE2
    sage_gather_kernel<<<gatherBlocks, 256>>>(B1, S1);
    gemm_dual<<<gemmBlocks, 256>>>(S1, W2l_hi, W2l_lo, S3, W2r_hi, W2r_lo,
                                   s2_bl, S2, nullptr, N_NODES);

    // pool + classifier
    dim3 pg(N_GRAPHS, 8);
    pool_kernel<<<pg, 128>>>(S2);
    mlp_kernel<<<N_GRAPHS, 256>>>(c_w0, c_b0, c_w1, c_b1, c_w2, c_b2, c_w3, c_b3,
                                  bn0g, bn0b, bn1g, bn1b, bn2g, bn2b, out);
}

// round 10
// speedup vs baseline: 1.2898x; 1.2226x over previous
#include <cuda_runtime.h>
#include <cuda_bf16.h>
#include <math.h>
#include <stdint.h>

// ---------------- constants ----------------
#define N_NODES  100000
#define N_EDGES  1600000
#define FEAT     128
#define N_GRAPHS 64
#define N_CLASSES 10

#define SCAN_BLK   1024
#define SCAN_NBLK  ((N_NODES + SCAN_BLK - 1) / SCAN_BLK)   // 98

// ---------------- device scratch ----------------
__device__ float g_S2[(size_t)N_NODES * FEAT];                 // final layer fp32 (for pool)
__device__ __nv_bfloat16 g_B1[(size_t)N_NODES * FEAT];         // gcn gemm out
__device__ __nv_bfloat16 g_B2[(size_t)N_NODES * FEAT];         // gcn layer out (h1)
__device__ __nv_bfloat16 g_B3[(size_t)N_NODES * FEAT];         // sage1 out (h2)
__device__ __nv_bfloat16 g_Bagg[(size_t)N_NODES * FEAT];       // aggregation scratch

// pre-split weights, k-major: [pair 0..63][row 0..127]
__device__ uint32_t g_Wg_hi[64 * 128],  g_Wg_lo[64 * 128];
__device__ uint32_t g_W1l_hi[64 * 128], g_W1l_lo[64 * 128];
__device__ uint32_t g_W1r_hi[64 * 128], g_W1r_lo[64 * 128];
__device__ uint32_t g_W2l_hi[64 * 128], g_W2l_lo[64 * 128];
__device__ uint32_t g_W2r_hi[64 * 128], g_W2r_lo[64 * 128];

__device__ int   g_src[N_EDGES];
__device__ int   g_dst[N_EDGES];
__device__ int   g_csr[N_EDGES];
__device__ int   g_batch[N_NODES];
__device__ int   g_indeg[N_NODES];
__device__ int   g_rowstart[N_NODES + 1];
__device__ int   g_pos[N_NODES];
__device__ float g_dinv[N_NODES];
__device__ float g_rcnt[N_NODES];
__device__ float g_pool[N_GRAPHS * FEAT];
__device__ int   g_gcnt[N_GRAPHS];
__device__ int   g_blocksum[SCAN_NBLK];
__device__ int   g_blockoff[SCAN_NBLK];
__device__ int   g_is64;

// ---------------- helpers ----------------
__device__ __forceinline__ void split2(float x, float y, uint32_t& hi, uint32_t& lo) {
    __nv_bfloat162 h = __floats2bfloat162_rn(x, y);
    float2 hf = __bfloat1622float2(h);
    __nv_bfloat162 l = __floats2bfloat162_rn(x - hf.x, y - hf.y);
    hi = *reinterpret_cast<uint32_t*>(&h);
    lo = *reinterpret_cast<uint32_t*>(&l);
}

__device__ __forceinline__ void mma_bf16(float* c, const uint32_t* a, const uint32_t* b) {
    asm volatile(
        "mma.sync.aligned.m16n8k16.row.col.f32.bf16.bf16.f32 "
        "{%0,%1,%2,%3}, {%4,%5,%6,%7}, {%8,%9}, {%0,%1,%2,%3};\n"
        : "+f"(c[0]), "+f"(c[1]), "+f"(c[2]), "+f"(c[3])
        : "r"(a[0]), "r"(a[1]), "r"(a[2]), "r"(a[3]), "r"(b[0]), "r"(b[1]));
}

// ---------------- merged weight prepack (5 matrices in one launch) ----------------
__global__ void prepack_all(const float* __restrict__ Wg,
                            const float* __restrict__ W1l, const float* __restrict__ W1r,
                            const float* __restrict__ W2l, const float* __restrict__ W2r)
{
    int widx = blockIdx.x >> 5;                       // 0..4
    int idx  = (blockIdx.x & 31) * 256 + threadIdx.x; // 0..8191
    const float* W; uint32_t *hi, *lo;
    switch (widx) {
        case 0: W = Wg;  hi = g_Wg_hi;  lo = g_Wg_lo;  break;
        case 1: W = W1l; hi = g_W1l_hi; lo = g_W1l_lo; break;
        case 2: W = W1r; hi = g_W1r_hi; lo = g_W1r_lo; break;
        case 3: W = W2l; hi = g_W2l_hi; lo = g_W2l_lo; break;
        default:W = W2r; hi = g_W2l_hi == nullptr ? nullptr : g_W2r_hi; lo = g_W2r_lo; break;
    }
    int p = idx >> 7;        // k-pair 0..63
    int r = idx & 127;       // row 0..127
    float x = W[r * 128 + p * 2];
    float y = W[r * 128 + p * 2 + 1];
    uint32_t h, l;
    split2(x, y, h, l);
    hi[p * 128 + r] = h;
    lo[p * 128 + r] = l;
}

// ---------------- index dtype detection ----------------
__global__ void detect_kernel(const void* ei) {
    const unsigned long long* p = (const unsigned long long*)ei;
    unsigned long long v = p[threadIdx.x];
    unsigned int hi = (unsigned int)(v >> 32);
    unsigned int any = __ballot_sync(0xffffffffu, hi != 0u);
    __shared__ int s_any;
    if (threadIdx.x == 0) s_any = 0;
    __syncthreads();
    if (any != 0u && (threadIdx.x & 31) == 0) atomicOr(&s_any, 1);
    __syncthreads();
    if (threadIdx.x == 0) g_is64 = s_any ? 0 : 1;
}

__global__ void zero_kernel() {
    int i = blockIdx.x * blockDim.x + threadIdx.x;
    if (i < N_NODES) g_indeg[i] = 0;
    if (i < N_GRAPHS * FEAT) g_pool[i] = 0.0f;
}

__global__ void convert_hist_kernel(const void* ei, const void* bt) {
    int i = blockIdx.x * blockDim.x + threadIdx.x;
    const int is64 = g_is64;
    if (i < N_EDGES) {
        int s, d;
        if (is64) {
            s = (int)((const long long*)ei)[i];
            d = (int)((const long long*)ei)[(size_t)N_EDGES + i];
        } else {
            s = ((const int*)ei)[i];
            d = ((const int*)ei)[N_EDGES + i];
        }
        g_src[i] = s;
        g_dst[i] = d;
        atomicAdd(&g_indeg[d], 1);
    }
    if (i < N_NODES) {
        g_batch[i] = is64 ? (int)((const long long*)bt)[i] : ((const int*)bt)[i];
    }
}

// ---------------- 3-phase multi-block scan ----------------
__global__ __launch_bounds__(SCAN_BLK) void scan1_kernel() {
    __shared__ int warp_s[32];
    int idx = blockIdx.x * SCAN_BLK + threadIdx.x;
    int v = (idx < N_NODES) ? g_indeg[idx] : 0;
#pragma unroll
    for (int o = 16; o > 0; o >>= 1) v += __shfl_down_sync(0xffffffffu, v, o);
    int wid = threadIdx.x >> 5, lane = threadIdx.x & 31;
    if (lane == 0) warp_s[wid] = v;
    __syncthreads();
    if (wid == 0) {
        int s = (lane < SCAN_BLK / 32) ? warp_s[lane] : 0;
#pragma unroll
        for (int o = 16; o > 0; o >>= 1) s += __shfl_down_sync(0xffffffffu, s, o);
        if (lane == 0) g_blocksum[blockIdx.x] = s;
    }
}

__global__ void scan2_kernel() {
    __shared__ int sm[SCAN_NBLK];
    int t = threadIdx.x;
    int v = (t < SCAN_NBLK) ? g_blocksum[t] : 0;
    if (t < SCAN_NBLK) sm[t] = v;
    __syncthreads();
    if (t == 0) {
        int run = 0;
        for (int i = 0; i < SCAN_NBLK; i++) { int c = sm[i]; sm[i] = run; run += c; }
        g_rowstart[N_NODES] = run;
    }
    __syncthreads();
    if (t < SCAN_NBLK) g_blockoff[t] = sm[t];
}

__global__ __launch_bounds__(SCAN_BLK) void scan3_kernel() {
    __shared__ int warp_s[32];
    int idx = blockIdx.x * SCAN_BLK + threadIdx.x;
    int wid = threadIdx.x >> 5, lane = threadIdx.x & 31;
    int c = (idx < N_NODES) ? g_indeg[idx] : 0;
    int v = c;
#pragma unroll
    for (int o = 1; o < 32; o <<= 1) {
        int u = __shfl_up_sync(0xffffffffu, v, o);
        if (lane >= o) v += u;
    }
    if (lane == 31) warp_s[wid] = v;
    __syncthreads();
    if (wid == 0) {
        int s = (lane < SCAN_BLK / 32) ? warp_s[lane] : 0;
#pragma unroll
        for (int o = 1; o < 32; o <<= 1) {
            int u = __shfl_up_sync(0xffffffffu, s, o);
            if (lane >= o) s += u;
        }
        if (lane < SCAN_BLK / 32) warp_s[lane] = s;
    }
    __syncthreads();
    int excl = v - c + (wid > 0 ? warp_s[wid - 1] : 0) + g_blockoff[blockIdx.x];
    if (idx < N_NODES) {
        g_rowstart[idx] = excl;
        g_pos[idx]      = excl;
        g_dinv[idx]     = rsqrtf((float)c + 1.0f);
        g_rcnt[idx]     = 1.0f / (float)max(c, 1);
    }
}

__global__ void scatter_kernel() {
    int e = blockIdx.x * blockDim.x + threadIdx.x;
    if (e < N_EDGES) {
        int d = g_dst[e];
        int p = atomicAdd(&g_pos[d], 1);
        g_csr[p] = g_src[e];
    }
}

// ---------------- GEMM fragment core (A bf16 in smem, W split hi/lo) ----------------
#define SMW 20

// ---------------- GCN GEMM: A fp32 -> round bf16; out bf16 only ----------------
__global__ __launch_bounds__(256, 2) void gemm_gcn(
    const float* __restrict__ A,
    const uint32_t* __restrict__ Whi, const uint32_t* __restrict__ Wlo,
    __nv_bfloat16* __restrict__ outb, int M)
{
    __shared__ uint32_t sAh[128][SMW];
    __shared__ uint32_t sWhi[128][SMW], sWlo[128][SMW];

    const int t    = threadIdx.x;
    const int warp = t >> 5;
    const int lane = t & 31;
    const int wm   = warp >> 1;
    const int wn   = warp & 1;
    const int m0   = blockIdx.x * 128;
    const int r    = lane >> 2;
    const int kq   = lane & 3;

    float acc[2][8][4];
#pragma unroll
    for (int i = 0; i < 2; i++)
#pragma unroll
        for (int j = 0; j < 8; j++)
#pragma unroll
            for (int q = 0; q < 4; q++) acc[i][j][q] = 0.0f;

    for (int k0 = 0; k0 < 128; k0 += 32) {
        // A tile 128x32 fp32 -> bf16 round (1024 float4 slots, 4/thread)
#pragma unroll
        for (int i = 0; i < 4; i++) {
            int slot = t + i * 256;
            int row  = slot >> 3;
            int c4   = slot & 7;
            int ar   = m0 + row; if (ar >= M) ar = M - 1;
            float4 av = __ldg((const float4*)(A + (size_t)ar * 128 + k0 + c4 * 4));
            __nv_bfloat162 h0 = __floats2bfloat162_rn(av.x, av.y);
            __nv_bfloat162 h1 = __floats2bfloat162_rn(av.z, av.w);
            sAh[row][c4 * 2]     = *reinterpret_cast<uint32_t*>(&h0);
            sAh[row][c4 * 2 + 1] = *reinterpret_cast<uint32_t*>(&h1);
        }
        // W tile prepacked (2048 u32 per array, 8/thread)
        {
            int kb = k0 >> 1;
#pragma unroll
            for (int i = 0; i < 8; i++) {
                int idx = t + i * 256;
                int row = idx & 127;
                int w   = idx >> 7;
                sWhi[row][w] = __ldg(Whi + (kb + w) * 128 + row);
                sWlo[row][w] = __ldg(Wlo + (kb + w) * 128 + row);
            }
        }
        __syncthreads();

#pragma unroll
        for (int kk = 0; kk < 32; kk += 16) {
            const int kw = kk >> 1;
            uint32_t ah[2][4];
#pragma unroll
            for (int mt = 0; mt < 2; mt++) {
                int mr = wm * 32 + mt * 16;
                ah[mt][0] = sAh[mr + r][kw + kq];
                ah[mt][1] = sAh[mr + r + 8][kw + kq];
                ah[mt][2] = sAh[mr + r][kw + kq + 4];
                ah[mt][3] = sAh[mr + r + 8][kw + kq + 4];
            }
#pragma unroll
            for (int g = 0; g < 2; g++) {
                uint32_t bh[4][2], bl[4][2];
#pragma unroll
                for (int n2 = 0; n2 < 4; n2++) {
                    int nr = wn * 64 + g * 32 + n2 * 8 + r;
                    bh[n2][0] = sWhi[nr][kw + kq];
                    bh[n2][1] = sWhi[nr][kw + kq + 4];
                    bl[n2][0] = sWlo[nr][kw + kq];
                    bl[n2][1] = sWlo[nr][kw + kq + 4];
                }
#pragma unroll
                for (int mt = 0; mt < 2; mt++)
#pragma unroll
                    for (int n2 = 0; n2 < 4; n2++) {
                        float* c = acc[mt][g * 4 + n2];
                        mma_bf16(c, ah[mt], bh[n2]);
                        mma_bf16(c, ah[mt], bl[n2]);
                    }
            }
        }
        __syncthreads();
    }

#pragma unroll
    for (int mt = 0; mt < 2; mt++) {
#pragma unroll
        for (int nt = 0; nt < 8; nt++) {
            int gcol = wn * 64 + nt * 8 + kq * 2;
            int grow = m0 + wm * 32 + mt * 16 + r;
            if (grow < M)
                *(__nv_bfloat162*)(outb + (size_t)grow * 128 + gcol) =
                    __floats2bfloat162_rn(acc[mt][nt][0], acc[mt][nt][1]);
            int grow2 = grow + 8;
            if (grow2 < M)
                *(__nv_bfloat162*)(outb + (size_t)grow2 * 128 + gcol) =
                    __floats2bfloat162_rn(acc[mt][nt][2], acc[mt][nt][3]);
        }
    }
}

// ---------------- dual GEMM: A1,A2 bf16; out = A1@W1 + A2@W2 + bias ----------------
__global__ __launch_bounds__(256, 2) void gemm_dual(
    const __nv_bfloat16* __restrict__ A1,
    const uint32_t* __restrict__ W1hi, const uint32_t* __restrict__ W1lo,
    const __nv_bfloat16* __restrict__ A2,
    const uint32_t* __restrict__ W2hi, const uint32_t* __restrict__ W2lo,
    const float* __restrict__ bias,
    float* __restrict__ out, __nv_bfloat16* __restrict__ outb, int M)
{
    __shared__ uint32_t sAh[128][SMW];
    __shared__ uint32_t sWhi[128][SMW], sWlo[128][SMW];

    const int t    = threadIdx.x;
    const int warp = t >> 5;
    const int lane = t & 31;
    const int wm   = warp >> 1;
    const int wn   = warp & 1;
    const int m0   = blockIdx.x * 128;
    const int r    = lane >> 2;
    const int kq   = lane & 3;

    float acc[2][8][4];
#pragma unroll
    for (int i = 0; i < 2; i++)
#pragma unroll
        for (int j = 0; j < 8; j++)
#pragma unroll
            for (int q = 0; q < 4; q++) acc[i][j][q] = 0.0f;

    for (int pass = 0; pass < 2; pass++) {
        const __nv_bfloat16* A = pass ? A2 : A1;
        const uint32_t* Whi = pass ? W2hi : W1hi;
        const uint32_t* Wlo = pass ? W2lo : W1lo;
        for (int k0 = 0; k0 < 128; k0 += 32) {
            // A tile 128x32 bf16 = 512 uint4 slots, 2/thread (coalesced 16B)
#pragma unroll
            for (int i = 0; i < 2; i++) {
                int slot = t + i * 256;      // 0..511
                int row  = slot >> 2;        // 0..127
                int c16  = slot & 3;         // 16B chunk (8 bf16)
                int ar   = m0 + row; if (ar >= M) ar = M - 1;
                uint4 v = __ldg((const uint4*)(A + (size_t)ar * 128 + k0) + c16);
                *(uint4*)&sAh[row][c16 * 4] = v;
            }
            // W tile prepacked
            {
                int kb = k0 >> 1;
#pragma unroll
                for (int i = 0; i < 8; i++) {
                    int idx = t + i * 256;
                    int row = idx & 127;
                    int w   = idx >> 7;
                    sWhi[row][w] = __ldg(Whi + (kb + w) * 128 + row);
                    sWlo[row][w] = __ldg(Wlo + (kb + w) * 128 + row);
                }
            }
            __syncthreads();

#pragma unroll
            for (int kk = 0; kk < 32; kk += 16) {
                const int kw = kk >> 1;
                uint32_t ah[2][4];
#pragma unroll
                for (int mt = 0; mt < 2; mt++) {
                    int mr = wm * 32 + mt * 16;
                    ah[mt][0] = sAh[mr + r][kw + kq];
                    ah[mt][1] = sAh[mr + r + 8][kw + kq];
                    ah[mt][2] = sAh[mr + r][kw + kq + 4];
                    ah[mt][3] = sAh[mr + r + 8][kw + kq + 4];
                }
#pragma unroll
                for (int g = 0; g < 2; g++) {
                    uint32_t bh[4][2], bl[4][2];
#pragma unroll
                    for (int n2 = 0; n2 < 4; n2++) {
                        int nr = wn * 64 + g * 32 + n2 * 8 + r;
                        bh[n2][0] = sWhi[nr][kw + kq];
                        bh[n2][1] = sWhi[nr][kw + kq + 4];
                        bl[n2][0] = sWlo[nr][kw + kq];
                        bl[n2][1] = sWlo[nr][kw + kq + 4];
                    }
#pragma unroll
                    for (int mt = 0; mt < 2; mt++)
#pragma unroll
                        for (int n2 = 0; n2 < 4; n2++) {
                            float* c = acc[mt][g * 4 + n2];
                            mma_bf16(c, ah[mt], bh[n2]);
                            mma_bf16(c, ah[mt], bl[n2]);
                        }
                }
            }
            __syncthreads();
        }
    }

#pragma unroll
    for (int mt = 0; mt < 2; mt++) {
#pragma unroll
        for (int nt = 0; nt < 8; nt++) {
            int gcol = wn * 64 + nt * 8 + kq * 2;
            float b0 = bias[gcol], b1 = bias[gcol + 1];
            int grow = m0 + wm * 32 + mt * 16 + r;
            if (grow < M) {
                float v0 = acc[mt][nt][0] + b0;
                float v1 = acc[mt][nt][1] + b1;
                if (out) {
                    float* p = out + (size_t)grow * 128 + gcol;
                    p[0] = v0; p[1] = v1;
                }
                if (outb) *(__nv_bfloat162*)(outb + (size_t)grow * 128 + gcol) =
                    __floats2bfloat162_rn(v0, v1);
            }
            int grow2 = grow + 8;
            if (grow2 < M) {
                float v0 = acc[mt][nt][2] + b0;
                float v1 = acc[mt][nt][3] + b1;
                if (out) {
                    float* p = out + (size_t)grow2 * 128 + gcol;
                    p[0] = v0; p[1] = v1;
                }
                if (outb) *(__nv_bfloat162*)(outb + (size_t)grow2 * 128 + gcol) =
                    __floats2bfloat162_rn(v0, v1);
            }
        }
    }
}

// ---------------- CSR gathers (bf16 in, bf16 out, fp32 accumulate) ----------------
__device__ __forceinline__ void acc_bf16row(float4& acc, const __nv_bfloat16* __restrict__ hb,
                                            int s, int lane, float nm) {
    uint2 raw = __ldg((const uint2*)(hb + (size_t)s * 128) + lane);
    float2 p0 = __bfloat1622float2(*reinterpret_cast<__nv_bfloat162*>(&raw.x));
    float2 p1 = __bfloat1622float2(*reinterpret_cast<__nv_bfloat162*>(&raw.y));
    acc.x += p0.x * nm; acc.y += p0.y * nm;
    acc.z += p1.x * nm; acc.w += p1.y * nm;
}

__device__ __forceinline__ void store_bf16row(__nv_bfloat16* __restrict__ outb,
                                              int w, int lane, const float4& acc) {
    uint2 ob;
    __nv_bfloat162 q0 = __floats2bfloat162_rn(acc.x, acc.y);
    __nv_bfloat162 q1 = __floats2bfloat162_rn(acc.z, acc.w);
    ob.x = *reinterpret_cast<uint32_t*>(&q0);
    ob.y = *reinterpret_cast<uint32_t*>(&q1);
    *((uint2*)(outb + (size_t)w * 128) + lane) = ob;
}

__global__ __launch_bounds__(256) void gcn_gather_kernel(
    const __nv_bfloat16* __restrict__ xwb, __nv_bfloat16* __restrict__ outb,
    const float* __restrict__ bias)
{
    int w = (blockIdx.x * blockDim.x + threadIdx.x) >> 5;
    int lane = threadIdx.x & 31;
    if (w >= N_NODES) return;
    int beg = g_rowstart[w], end = g_rowstart[w + 1];
    float dn = g_dinv[w];
    float4 acc = make_float4(0.f, 0.f, 0.f, 0.f);
    for (int b = beg; b < end; b += 32) {
        int nb = min(32, end - b);
        int s_l = 0; float d_l = 0.f;
        if (b + lane < end) { s_l = g_csr[b + lane]; d_l = g_dinv[s_l]; }
        for (int j = 0; j < nb; j++) {
            int   s  = __shfl_sync(0xffffffffu, s_l, j);
            float nm = __shfl_sync(0xffffffffu, d_l, j) * dn;
            acc_bf16row(acc, xwb, s, lane, nm);
        }
    }
    // self-loop term + bias (self row from bf16 mirror)
    float4 bv = *(const float4*)(bias + lane * 4);
    acc.x += bv.x; acc.y += bv.y; acc.z += bv.z; acc.w += bv.w;
    acc_bf16row(acc, xwb, w, lane, dn * dn);
    store_bf16row(outb, w, lane, acc);
}

__global__ __launch_bounds__(256) void sage_gather_kernel(
    const __nv_bfloat16* __restrict__ hb, __nv_bfloat16* __restrict__ outb)
{
    int w = (blockIdx.x * blockDim.x + threadIdx.x) >> 5;
    int lane = threadIdx.x & 31;
    if (w >= N_NODES) return;
    int beg = g_rowstart[w], end = g_rowstart[w + 1];
    float4 acc = make_float4(0.f, 0.f, 0.f, 0.f);
    for (int b = beg; b < end; b += 32) {
        int nb = min(32, end - b);
        int s_l = 0;
        if (b + lane < end) s_l = g_csr[b + lane];
        for (int j = 0; j < nb; j++) {
            int s = __shfl_sync(0xffffffffu, s_l, j);
            acc_bf16row(acc, hb, s, lane, 1.0f);
        }
    }
    float rc = g_rcnt[w];
    acc.x *= rc; acc.y *= rc; acc.z *= rc; acc.w *= rc;
    store_bf16row(outb, w, lane, acc);
}

// ---------------- pooling ----------------
__device__ __forceinline__ int lower_bound_batch(int val) {
    int lo = 0, hi = N_NODES;
    while (lo < hi) {
        int mid = (lo + hi) >> 1;
        if (g_batch[mid] < val) lo = mid + 1; else hi = mid;
    }
    return lo;
}

__global__ void pool_kernel(const float* __restrict__ h) {
    int g = blockIdx.x;
    int part = blockIdx.y;
    int f = threadIdx.x;
    int lo = lower_bound_batch(g);
    int hi = lower_bound_batch(g + 1);
    float acc = 0.f;
    for (int n = lo + part; n < hi; n += 8) acc += h[(size_t)n * 128 + f];
    atomicAdd(&g_pool[g * 128 + f], acc);
    if (part == 0 && f == 0) g_gcnt[g] = max(hi - lo, 1);
}

// ---------------- classifier MLP + softmax ----------------
__global__ void mlp_kernel(
    const float* __restrict__ w0, const float* __restrict__ b0,
    const float* __restrict__ w1, const float* __restrict__ b1,
    const float* __restrict__ w2, const float* __restrict__ b2,
    const float* __restrict__ w3, const float* __restrict__ b3,
    const float* __restrict__ bn0g, const float* __restrict__ bn0b,
    const float* __restrict__ bn1g, const float* __restrict__ bn1b,
    const float* __restrict__ bn2g, const float* __restrict__ bn2b,
    float* __restrict__ out)
{
    __shared__ float sin_[128], h0[200], h1[100], h2[50], lg[10];
    int g = blockIdx.x, t = threadIdx.x;
    if (t < 128) sin_[t] = g_pool[g * 128 + t] / (float)g_gcnt[g];
    __syncthreads();
    const float bnc = rsqrtf(1.0f + 1e-5f);
    if (t < 200) {
        float s = b0[t];
        const float* wr = w0 + (size_t)t * 128;
#pragma unroll 4
        for (int k = 0; k < 128; k++) s += wr[k] * sin_[k];
        h0[t] = tanhf(s * bn0g[t] * bnc + bn0b[t]);
    }
    __syncthreads();
    if (t < 100) {
        float s = b1[t];
        const float* wr = w1 + (size_t)t * 200;
#pragma unroll 4
        for (int k = 0; k < 200; k++) s += wr[k] * h0[k];
        h1[t] = tanhf(s * bn1g[t] * bnc + bn1b[t]);
    }
    __syncthreads();
    if (t < 50) {
        float s = b2[t];
        const float* wr = w2 + (size_t)t * 100;
#pragma unroll 4
        for (int k = 0; k < 100; k++) s += wr[k] * h1[k];
        h2[t] = tanhf(s * bn2g[t] * bnc + bn2b[t]);
    }
    __syncthreads();
    if (t < 10) {
        float s = b3[t];
        const float* wr = w3 + (size_t)t * 50;
#pragma unroll
        for (int k = 0; k < 50; k++) s += wr[k] * h2[k];
        lg[t] = s;
    }
    __syncthreads();
    if (t == 0) {
        float m = lg[0];
        for (int c = 1; c < N_CLASSES; c++) m = fmaxf(m, lg[c]);
        float e[N_CLASSES];
        float sum = 0.f;
        for (int c = 0; c < N_CLASSES; c++) { e[c] = expf(lg[c] - m); sum += e[c]; }
        float inv = 1.0f / sum;
        for (int c = 0; c < N_CLASSES; c++) out[g * N_CLASSES + c] = e[c] * inv;
    }
}

// ---------------- launch ----------------
extern "C" void kernel_launch(void* const* d_in, const int* in_sizes, int n_in,
                              void* d_out, int out_size)
{
    const float* x       = (const float*)d_in[0];
    const void*  ei      = d_in[1];
    const void*  bt      = d_in[2];
    const float* gcn_w   = (const float*)d_in[3];
    const float* gcn_b   = (const float*)d_in[4];
    const float* s1_wl   = (const float*)d_in[5];
    const float* s1_bl   = (const float*)d_in[6];
    const float* s1_wr   = (const float*)d_in[7];
    const float* s2_wl   = (const float*)d_in[8];
    const float* s2_bl   = (const float*)d_in[9];
    const float* s2_wr   = (const float*)d_in[10];
    const float* c_w0 = (const float*)d_in[11]; const float* c_b0 = (const float*)d_in[12];
    const float* c_w1 = (const float*)d_in[13]; const float* c_b1 = (const float*)d_in[14];
    const float* c_w2 = (const float*)d_in[15]; const float* c_b2 = (const float*)d_in[16];
    const float* c_w3 = (const float*)d_in[17]; const float* c_b3 = (const float*)d_in[18];
    const float* bn0g = (const float*)d_in[19]; const float* bn0b = (const float*)d_in[20];
    const float* bn1g = (const float*)d_in[21]; const float* bn1b = (const float*)d_in[22];
    const float* bn2g = (const float*)d_in[23]; const float* bn2b = (const float*)d_in[24];
    float* out = (float*)d_out;

    float *S2;
    __nv_bfloat16 *B1, *B2, *B3, *Bagg;
    uint32_t *Wg_hi, *Wg_lo, *W1l_hi, *W1l_lo, *W1r_hi, *W1r_lo;
    uint32_t *W2l_hi, *W2l_lo, *W2r_hi, *W2r_lo;
    cudaGetSymbolAddress((void**)&S2, g_S2);
    cudaGetSymbolAddress((void**)&B1, g_B1);
    cudaGetSymbolAddress((void**)&B2, g_B2);
    cudaGetSymbolAddress((void**)&B3, g_B3);
    cudaGetSymbolAddress((void**)&Bagg, g_Bagg);
    cudaGetSymbolAddress((void**)&Wg_hi, g_Wg_hi);   cudaGetSymbolAddress((void**)&Wg_lo, g_Wg_lo);
    cudaGetSymbolAddress((void**)&W1l_hi, g_W1l_hi); cudaGetSymbolAddress((void**)&W1l_lo, g_W1l_lo);
    cudaGetSymbolAddress((void**)&W1r_hi, g_W1r_hi); cudaGetSymbolAddress((void**)&W1r_lo, g_W1r_lo);
    cudaGetSymbolAddress((void**)&W2l_hi, g_W2l_hi); cudaGetSymbolAddress((void**)&W2l_lo, g_W2l_lo);
    cudaGetSymbolAddress((void**)&W2r_hi, g_W2r_hi); cudaGetSymbolAddress((void**)&W2r_lo, g_W2r_lo);

    static cudaStream_t s_side = nullptr;
    static cudaEvent_t  s_fork = nullptr, s_join = nullptr;
    if (s_side == nullptr) {
        cudaStreamCreateWithFlags(&s_side, cudaStreamNonBlocking);
        cudaEventCreateWithFlags(&s_fork, cudaEventDisableTiming);
        cudaEventCreateWithFlags(&s_join, cudaEventDisableTiming);
    }

    const int TB = 256;
    const int nodeBlocks   = (N_NODES + TB - 1) / TB;
    const int edgeBlocks   = (N_EDGES + TB - 1) / TB;
    const int gatherBlocks = (N_NODES + 7) / 8;
    const int gemmBlocks   = (N_NODES + 127) / 128;

    // fork at t=0: side stream does prepack + GCN GEMM, hidden under CSR build
    cudaEventRecord(s_fork, 0);
    cudaStreamWaitEvent(s_side, s_fork, 0);
    prepack_all<<<160, 256, 0, s_side>>>(gcn_w, s1_wl, s1_wr, s2_wl, s2_wr);
    gemm_gcn<<<gemmBlocks, 256, 0, s_side>>>(x, Wg_hi, Wg_lo, B1, N_NODES);

    // main stream: index prep + CSR build
    detect_kernel<<<1, 256>>>(ei);
    zero_kernel<<<nodeBlocks, TB>>>();
    convert_hist_kernel<<<edgeBlocks, TB>>>(ei, bt);
    scan1_kernel<<<SCAN_NBLK, SCAN_BLK>>>();
    scan2_kernel<<<1, 128>>>();
    scan3_kernel<<<SCAN_NBLK, SCAN_BLK>>>();
    scatter_kernel<<<edgeBlocks, TB>>>();

    cudaEventRecord(s_join, s_side);
    cudaStreamWaitEvent(0, s_join, 0);

    // GCN aggregate: B2 = norm-agg(B1) + self(B1)*dinv^2 + bias
    gcn_gather_kernel<<<gatherBlocks, 256>>>(B1, B2, gcn_b);

    // SAGE1: Bagg = mean-agg(B2); B3 = Bagg@W1l + bl + B2@W1r
    sage_gather_kernel<<<gatherBlocks, 256>>>(B2, Bagg);
    gemm_dual<<<gemmBlocks, 256>>>(Bagg, W1l_hi, W1l_lo, B2, W1r_hi, W1r_lo,
                                   s1_bl, nullptr, B3, N_NODES);

    // SAGE2: Bagg = mean-agg(B3); S2 = Bagg@W2l + bl + B3@W2r (fp32 for pool)
    sage_gather_kernel<<<gatherBlocks, 256>>>(B3, Bagg);
    gemm_dual<<<gemmBlocks, 256>>>(Bagg, W2l_hi, W2l_lo, B3, W2r_hi, W2r_lo,
                                   s2_bl, S2, nullptr, N_NODES);

    // pool + classifier
    dim3 pg(N_GRAPHS, 8);
    pool_kernel<<<pg, 128>>>(S2);
    mlp_kernel<<<N_GRAPHS, 256>>>(c_w0, c_b0, c_w1, c_b1, c_w2, c_b2, c_w3, c_b3,
                                  bn0g, bn0b, bn1g, bn1b, bn2g, bn2b, out);
}